// round 2
// baseline (speedup 1.0000x reference)
#include <cuda_runtime.h>
#include <cstdint>

// ---------------------------------------------------------------------------
// NetVLAD on GB300 — round 1: correct fp32 pipeline, conv via shifted-GEMM
// with packed f32x2 FMAs (FFMA2). Output layout: [vlad | x_enc].
// ---------------------------------------------------------------------------

#define N_IMG   16
#define CHN     512
#define HWP     1024      // 32*32 positions per image
#define KCL     64        // clusters

// Scratch (static device globals; no allocation allowed)
__device__ float g_wT1[9 * 512 * 512];   // [tap][ic][oc]
__device__ float g_wT2[9 * 512 * 512];
__device__ float g_h[N_IMG * CHN * HWP]; // conv1 output (post BN+ReLU)
__device__ float g_invn[N_IMG * HWP];    // 1/max(||x_enc[:, l]||, eps)
__device__ float g_sa[N_IMG * KCL * HWP];
__device__ float g_ssum[N_IMG * KCL];
__device__ float g_vlad[N_IMG * KCL * CHN];
__device__ float g_rowss[N_IMG * KCL];
__device__ float g_bns[CHN];
__device__ float g_bnb[CHN];

// -------------------- packed f32x2 helpers --------------------
__device__ __forceinline__ unsigned long long fma2(unsigned long long a,
                                                   unsigned long long b,
                                                   unsigned long long c) {
    unsigned long long d;
    asm("fma.rn.f32x2 %0, %1, %2, %3;" : "=l"(d) : "l"(a), "l"(b), "l"(c));
    return d;
}
__device__ __forceinline__ unsigned long long pack2(float x, float y) {
    unsigned long long r;
    asm("mov.b64 %0, {%1, %2};" : "=l"(r) : "f"(x), "f"(y));
    return r;
}
__device__ __forceinline__ float2 unpack2(unsigned long long v) {
    float2 r;
    asm("mov.b64 {%0, %1}, %2;" : "=f"(r.x), "=f"(r.y) : "l"(v));
    return r;
}

// -------------------- prep: weight transpose + BN fold --------------------
// wT[tap][ic][oc] = w[oc][ic][tap]; also BN scale/bias.
__global__ void prep_kernel(const float* __restrict__ w1,
                            const float* __restrict__ w2,
                            const float* __restrict__ gamma,
                            const float* __restrict__ beta,
                            const float* __restrict__ mean,
                            const float* __restrict__ var) {
    int idx = blockIdx.x * 256 + threadIdx.x;
    const int per = 9 * 512 * 512;  // 2359296
    if (idx < 2 * per) {
        int which = (idx >= per) ? 1 : 0;
        int rem = idx - which * per;
        int tap = rem / (512 * 512);
        int r2 = rem % (512 * 512);
        int ic = r2 >> 9;
        int oc = r2 & 511;
        const float* w = which ? w2 : w1;
        float v = w[oc * 4608 + ic * 9 + tap];
        if (which) g_wT2[rem] = v; else g_wT1[rem] = v;
    }
    if (idx < CHN) {
        float inv = rsqrtf(var[idx] + 1e-5f);
        float s = gamma[idx] * inv;
        g_bns[idx] = s;
        g_bnb[idx] = beta[idx] - mean[idx] * s;
    }
}

// -------------------- conv 3x3 as 9 shifted GEMMs --------------------
// Tile: 128 oc x 128 positions, K-chunks of 8 input channels per tap.
// which==1: in = x (param), wT = g_wT1, out = g_h, fused BN+ReLU.
// which==2: in = g_h, wT = g_wT2, out = out_ext (x_enc region).
__global__ void __launch_bounds__(256, 2)
conv3x3_kernel(const float* __restrict__ in_ext, float* __restrict__ out_ext,
               int which) {
    __shared__ __align__(16) float As[8][128];
    __shared__ __align__(16) float Bs[8][128];

    const int n = blockIdx.z;
    const int oc0 = blockIdx.y * 128;
    const int p0 = blockIdx.x * 128;
    const int y0 = p0 >> 5;

    const float* in = (which == 1) ? in_ext : g_h;
    const float* wT = (which == 1) ? g_wT1 : g_wT2;
    float* out = (which == 1) ? g_h : out_ext;
    const int bnrelu = (which == 1);

    const float* inN = in + (size_t)n * CHN * HWP;
    float* outN = out + (size_t)n * CHN * HWP;

    const int tid = threadIdx.x;
    const int tx = tid & 15, ty = tid >> 4;
    const int mbase = ty * 8, pbase = tx * 8;

    unsigned long long acc[8][4];
#pragma unroll
    for (int i = 0; i < 8; i++)
#pragma unroll
        for (int j = 0; j < 4; j++) acc[i][j] = 0ULL;

    for (int tap = 0; tap < 9; tap++) {
        const int dy = tap / 3 - 1, dx = tap % 3 - 1;
        const float* wtap = wT + tap * (512 * 512) + oc0;
        for (int ic0 = 0; ic0 < 512; ic0 += 8) {
            // A tile: As[k][m] = wT[tap][ic0+k][oc0+m]   (coalesced)
#pragma unroll
            for (int r = 0; r < 4; r++) {
                int idx = tid + r * 256;
                int k = idx >> 7, m = idx & 127;
                As[k][m] = wtap[(ic0 + k) * 512 + m];
            }
            // B tile: shifted input with zero-pad masking  (coalesced)
#pragma unroll
            for (int r = 0; r < 4; r++) {
                int idx = tid + r * 256;
                int k = idx >> 7, p = idx & 127;
                int y = y0 + (p >> 5) + dy;
                int x = (p & 31) + dx;
                float v = 0.f;
                if ((unsigned)y < 32u && (unsigned)x < 32u)
                    v = inN[(ic0 + k) * HWP + (y << 5) + x];
                Bs[k][p] = v;
            }
            __syncthreads();
#pragma unroll
            for (int k = 0; k < 8; k++) {
                const unsigned long long* brow =
                    reinterpret_cast<const unsigned long long*>(&Bs[k][pbase]);
                unsigned long long pb0 = brow[0], pb1 = brow[1];
                unsigned long long pb2 = brow[2], pb3 = brow[3];
                float4 a0 = *reinterpret_cast<const float4*>(&As[k][mbase]);
                float4 a1 = *reinterpret_cast<const float4*>(&As[k][mbase + 4]);
                float av[8] = {a0.x, a0.y, a0.z, a0.w, a1.x, a1.y, a1.z, a1.w};
#pragma unroll
                for (int i = 0; i < 8; i++) {
                    unsigned long long pa = pack2(av[i], av[i]);
                    acc[i][0] = fma2(pa, pb0, acc[i][0]);
                    acc[i][1] = fma2(pa, pb1, acc[i][1]);
                    acc[i][2] = fma2(pa, pb2, acc[i][2]);
                    acc[i][3] = fma2(pa, pb3, acc[i][3]);
                }
            }
            __syncthreads();
        }
    }

#pragma unroll
    for (int i = 0; i < 8; i++) {
        int oc = oc0 + mbase + i;
        float s = bnrelu ? g_bns[oc] : 1.f;
        float b = bnrelu ? g_bnb[oc] : 0.f;
        float* orow = outN + (size_t)oc * HWP + p0 + pbase;
#pragma unroll
        for (int j = 0; j < 4; j++) {
            float2 u = unpack2(acc[i][j]);
            float v0 = u.x, v1 = u.y;
            if (bnrelu) {
                v0 = fmaxf(fmaf(v0, s, b), 0.f);
                v1 = fmaxf(fmaf(v1, s, b), 0.f);
            }
            orow[2 * j] = v0;
            orow[2 * j + 1] = v1;
        }
    }
}

// -------------------- channel-L2 + assign logits + softmax --------------------
// One thread per position l; accumulates ||x||^2 and 64 logits in registers.
__global__ void __launch_bounds__(128)
assign_softmax_kernel(const float* __restrict__ xenc, const float* __restrict__ wa) {
    __shared__ float s_w[8][64];
    const int n = blockIdx.x >> 3;
    const int l0 = (blockIdx.x & 7) * 128;
    const int tid = threadIdx.x;
    const int l = l0 + tid;
    const float* xN = xenc + (size_t)n * CHN * HWP;

    float s[64];
#pragma unroll
    for (int k = 0; k < 64; k++) s[k] = 0.f;
    float ss = 0.f;

    for (int c0 = 0; c0 < 512; c0 += 8) {
#pragma unroll
        for (int r = 0; r < 4; r++) {
            int idx = tid + r * 128;       // 0..511
            int cc = idx >> 6, k = idx & 63;
            s_w[cc][k] = wa[k * 512 + c0 + cc];
        }
        __syncthreads();
#pragma unroll
        for (int cc = 0; cc < 8; cc++) {
            float xv = xN[(c0 + cc) * HWP + l];
            ss = fmaf(xv, xv, ss);
#pragma unroll
            for (int k = 0; k < 64; k++) s[k] = fmaf(xv, s_w[cc][k], s[k]);
        }
        __syncthreads();
    }

    float invn = 1.f / fmaxf(sqrtf(ss), 1e-12f);
    g_invn[n * HWP + l] = invn;

    float mx = -1e30f;
#pragma unroll
    for (int k = 0; k < 64; k++) { s[k] *= invn; mx = fmaxf(mx, s[k]); }
    float sum = 0.f;
#pragma unroll
    for (int k = 0; k < 64; k++) { s[k] = expf(s[k] - mx); sum += s[k]; }
    float rs = 1.f / sum;
#pragma unroll
    for (int k = 0; k < 64; k++)
        g_sa[((size_t)n * 64 + k) * HWP + l] = s[k] * rs;
}

// -------------------- ssum[n,k] = sum_l sa (deterministic) --------------------
__global__ void ssum_kernel() {
    int row = blockIdx.x;                    // n*64+k
    int tid = threadIdx.x;                   // 256
    const float4* p = reinterpret_cast<const float4*>(g_sa + (size_t)row * HWP);
    float4 v = p[tid];
    float t = v.x + v.y + v.z + v.w;
    __shared__ float red[256];
    red[tid] = t;
    __syncthreads();
    for (int s = 128; s > 0; s >>= 1) {
        if (tid < s) red[tid] += red[tid + s];
        __syncthreads();
    }
    if (tid == 0) g_ssum[row] = red[0];
}

// -------------------- VLAD GEMM: vlad[n,k,c] = sum_l sa*xn - ssum*cent ------
// Block = (n, group of 8 clusters); warps own channels, lanes own l-strides.
__global__ void __launch_bounds__(256)
vlad_kernel(const float* __restrict__ xenc, const float* __restrict__ cent) {
    __shared__ float s_sa[8][1024];
    __shared__ float s_in[1024];
    const int n = blockIdx.x >> 3;
    const int k0 = (blockIdx.x & 7) * 8;
    const int tid = threadIdx.x;

    for (int i = tid; i < 1024; i += 256) s_in[i] = g_invn[n * HWP + i];
    for (int i = tid; i < 8192; i += 256) {
        int kk = i >> 10, l = i & 1023;
        s_sa[kk][l] = g_sa[((size_t)n * 64 + k0 + kk) * HWP + l];
    }
    __syncthreads();

    const int warp = tid >> 5, lane = tid & 31;
    const float* xN = xenc + (size_t)n * CHN * HWP;

    for (int c = warp; c < 512; c += 8) {
        float acc[8];
#pragma unroll
        for (int kk = 0; kk < 8; kk++) acc[kk] = 0.f;
        for (int l = lane; l < 1024; l += 32) {
            float xv = xN[c * HWP + l] * s_in[l];
#pragma unroll
            for (int kk = 0; kk < 8; kk++) acc[kk] = fmaf(xv, s_sa[kk][l], acc[kk]);
        }
#pragma unroll
        for (int kk = 0; kk < 8; kk++) {
            float v = acc[kk];
#pragma unroll
            for (int o = 16; o > 0; o >>= 1) v += __shfl_down_sync(0xffffffffu, v, o);
            if (lane == 0) {
                int k = k0 + kk;
                g_vlad[((size_t)n * 64 + k) * 512 + c] =
                    v - g_ssum[n * 64 + k] * cent[k * 512 + c];
            }
        }
    }
}

// -------------------- intra-normalization (per n,k row over c) --------------
__global__ void intra_kernel(float* __restrict__ out_vlad) {
    int row = blockIdx.x;                    // n*64+k
    int tid = threadIdx.x;                   // 256
    const float2* p = reinterpret_cast<const float2*>(g_vlad + (size_t)row * 512);
    float2 v = p[tid];
    float ssq = v.x * v.x + v.y * v.y;
    __shared__ float red[256];
    red[tid] = ssq;
    __syncthreads();
    for (int s = 128; s > 0; s >>= 1) {
        if (tid < s) red[tid] += red[tid + s];
        __syncthreads();
    }
    float ss = red[0];
    float inv = 1.f / fmaxf(sqrtf(ss), 1e-12f);
    float2* o = reinterpret_cast<float2*>(out_vlad + (size_t)row * 512);
    float2 w;
    w.x = v.x * inv;
    w.y = v.y * inv;
    o[tid] = w;
    if (tid == 0) g_rowss[row] = ss * inv * inv;
}

// -------------------- global L2 scale (per image) ---------------------------
__global__ void gscale_kernel(float* __restrict__ out_vlad) {
    int n = blockIdx.x;
    int tid = threadIdx.x;                   // 256
    __shared__ float red[64];
    __shared__ float gsc;
    if (tid < 64) red[tid] = g_rowss[n * 64 + tid];
    __syncthreads();
    if (tid == 0) {
        float t = 0.f;
        for (int i = 0; i < 64; i++) t += red[i];   // deterministic
        gsc = 1.f / fmaxf(sqrtf(t), 1e-12f);
    }
    __syncthreads();
    float g = gsc;
    float* o = out_vlad + (size_t)n * (KCL * CHN);
    for (int i = tid; i < KCL * CHN; i += 256) o[i] *= g;
}

// -------------------- launcher --------------------
extern "C" void kernel_launch(void* const* d_in, const int* in_sizes, int n_in,
                              void* d_out, int out_size) {
    const float* x     = (const float*)d_in[0];
    const float* w1    = (const float*)d_in[1];
    const float* gamma = (const float*)d_in[2];
    const float* beta  = (const float*)d_in[3];
    const float* mean  = (const float*)d_in[4];
    const float* var   = (const float*)d_in[5];
    const float* w2    = (const float*)d_in[6];
    const float* wa    = (const float*)d_in[7];
    const float* cent  = (const float*)d_in[8];

    float* out = (float*)d_out;
    float* out_vlad = out;                               // 16 * 32768
    float* out_xenc = out + (size_t)N_IMG * KCL * CHN;   // 16 * 512 * 1024

    prep_kernel<<<18432, 256>>>(w1, w2, gamma, beta, mean, var);

    dim3 cgrid(8, 4, N_IMG);
    conv3x3_kernel<<<cgrid, 256>>>(x, nullptr, 1);        // conv1 + BN + ReLU -> g_h
    conv3x3_kernel<<<cgrid, 256>>>(nullptr, out_xenc, 2); // conv2 -> x_enc

    assign_softmax_kernel<<<N_IMG * 8, 128>>>(out_xenc, wa);
    ssum_kernel<<<N_IMG * KCL, 256>>>();
    vlad_kernel<<<N_IMG * 8, 256>>>(out_xenc, cent);
    intra_kernel<<<N_IMG * KCL, 256>>>(out_vlad);
    gscale_kernel<<<N_IMG, 256>>>(out_vlad);
}

// round 4
// speedup vs baseline: 2.3533x; 2.3533x over previous
#include <cuda_runtime.h>
#include <cuda_bf16.h>
#include <cstdint>

// ---------------------------------------------------------------------------
// NetVLAD on GB300 — round 3: conv3x3 via mma.sync bf16x3 (HMMA path;
// tcgen05 unavailable because harness emits compute_103 PTX).
// ---------------------------------------------------------------------------

#define N_IMG   16
#define CHN     512
#define HWP     1024
#define KCL     64
#define KTOT    4608     // 9 taps * 512 ic
#define AP      40       // SMEM row pitch in bf16 (80B -> conflict-free ldmatrix)

// -------- device scratch --------
__device__ __align__(16) __nv_bfloat16 g_w1h[CHN * KTOT];
__device__ __align__(16) __nv_bfloat16 g_w1l[CHN * KTOT];
__device__ __align__(16) __nv_bfloat16 g_w2h[CHN * KTOT];
__device__ __align__(16) __nv_bfloat16 g_w2l[CHN * KTOT];
__device__ float g_h[N_IMG * CHN * HWP];
__device__ float g_invn[N_IMG * HWP];
__device__ float g_sa[N_IMG * KCL * HWP];
__device__ float g_ssum[N_IMG * KCL];
__device__ float g_vlad[N_IMG * KCL * CHN];
__device__ float g_rowss[N_IMG * KCL];
__device__ float g_bns[CHN];
__device__ float g_bnb[CHN];

// -------- helpers --------
__device__ __forceinline__ uint32_t smem_u32(const void* p) {
    uint32_t a;
    asm("{ .reg .u64 t; cvta.to.shared.u64 t, %1; cvt.u32.u64 %0, t; }"
        : "=r"(a) : "l"(p));
    return a;
}
__device__ __forceinline__ void ldm_x4(uint32_t r[4], uint32_t addr) {
    asm volatile("ldmatrix.sync.aligned.m8n8.x4.shared.b16 {%0,%1,%2,%3}, [%4];"
                 : "=r"(r[0]), "=r"(r[1]), "=r"(r[2]), "=r"(r[3]) : "r"(addr));
}
__device__ __forceinline__ void mma_bf16(float c[4], const uint32_t a[4],
                                         uint32_t b0, uint32_t b1) {
    asm volatile(
        "mma.sync.aligned.m16n8k16.row.col.f32.bf16.bf16.f32 "
        "{%0,%1,%2,%3}, {%4,%5,%6,%7}, {%8,%9}, {%0,%1,%2,%3};"
        : "+f"(c[0]), "+f"(c[1]), "+f"(c[2]), "+f"(c[3])
        : "r"(a[0]), "r"(a[1]), "r"(a[2]), "r"(a[3]), "r"(b0), "r"(b1));
}
__device__ __forceinline__ uint32_t pack_bf(__nv_bfloat16 a, __nv_bfloat16 b) {
    return (uint32_t)__bfloat16_as_ushort(a) |
           ((uint32_t)__bfloat16_as_ushort(b) << 16);
}

// ======================= prep: bf16 hi/lo split + BN fold =======================
__global__ void prep_kernel(const float* __restrict__ w1,
                            const float* __restrict__ w2,
                            const float* __restrict__ gamma,
                            const float* __restrict__ beta,
                            const float* __restrict__ mean,
                            const float* __restrict__ var) {
    int idx = blockIdx.x * 256 + threadIdx.x;
    const int per = CHN * KTOT;
    if (idx < 2 * per) {
        int which = (idx >= per) ? 1 : 0;
        int r = idx - which * per;
        int oc = r / KTOT;
        int rr = r - oc * KTOT;
        int tap = rr >> 9;
        int ic = rr & 511;
        const float* w = which ? w2 : w1;
        float v = w[oc * 4608 + ic * 9 + tap];
        __nv_bfloat16 h = __float2bfloat16(v);
        __nv_bfloat16 l = __float2bfloat16(v - __bfloat162float(h));
        if (which) { g_w2h[r] = h; g_w2l[r] = l; }
        else       { g_w1h[r] = h; g_w1l[r] = l; }
    }
    if (idx < CHN) {
        float inv = rsqrtf(var[idx] + 1e-5f);
        float s = gamma[idx] * inv;
        g_bns[idx] = s;
        g_bnb[idx] = beta[idx] - mean[idx] * s;
    }
}

// ======================= conv3x3 implicit GEMM (mma.sync bf16x3) ============
// CTA: 128 oc x 128 positions. 8 warps, warp tile 64x32 (2m x 4n layout).
// K chunks of 32 (tap-aligned). Grid: (8 ptiles, 4 octiles, 16 n).
__global__ void __launch_bounds__(256, 2)
conv_mma_kernel(const float* __restrict__ in_ext, float* __restrict__ out_ext,
                int which) {
    __shared__ __align__(16) __nv_bfloat16 sAh[128 * AP];
    __shared__ __align__(16) __nv_bfloat16 sAl[128 * AP];
    __shared__ __align__(16) __nv_bfloat16 sBh[128 * AP];
    __shared__ __align__(16) __nv_bfloat16 sBl[128 * AP];

    const int tid = threadIdx.x;
    const int lane = tid & 31, warp = tid >> 5;
    const int wm = warp >> 2, wn = warp & 3;
    const int n = blockIdx.z;
    const int oc0 = blockIdx.y * 128;
    const int p0 = blockIdx.x * 128;
    const int ybase = blockIdx.x * 4;

    const float* in = (which == 1) ? in_ext : g_h;
    const __nv_bfloat16* wh = (which == 1) ? g_w1h : g_w2h;
    const __nv_bfloat16* wl = (which == 1) ? g_w1l : g_w2l;
    float* out = (which == 1) ? g_h : out_ext;
    const float* inN = in + (size_t)n * CHN * HWP;
    float* outN = out + (size_t)n * CHN * HWP;

    const uint32_t aAh = smem_u32(sAh), aAl = smem_u32(sAl);
    const uint32_t aBh = smem_u32(sBh), aBl = smem_u32(sBl);

    // fill indices
    const int fa_oc = tid >> 1, fa_half = tid & 1;   // A: 16 bf16 per thread
    const int fb_p = tid & 127, fb_half = tid >> 7;  // B: 16 ic per thread

    // ldmatrix lane decomposition
    const int lt = lane >> 3, lr = lane & 7;
    // A tile addressing: row = m0 + (lt&1)*8 + lr, col = kk0 + (lt>>1)*8
    const int a_row_off = (lt & 1) * 8 + lr;
    const int a_col_off = (lt >> 1) * 8;
    // B tile addressing: row(n) = n0 + (lt>>1)*8 + lr, col = kk0 + (lt&1)*8
    const int b_row_off = (lt >> 1) * 8 + lr;
    const int b_col_off = (lt & 1) * 8;

    float C[4][4][4];
#pragma unroll
    for (int mi = 0; mi < 4; mi++)
#pragma unroll
        for (int ni = 0; ni < 4; ni++)
#pragma unroll
            for (int q = 0; q < 4; q++) C[mi][ni][q] = 0.f;

    for (int chunk = 0; chunk < 144; ++chunk) {
        const int k0 = chunk << 5;
        const int tap = k0 >> 9;
        const int icb = k0 & 511;
        const int dy = tap / 3 - 1, dx = tap % 3 - 1;

        // ---- A fill: 128 oc x 32 k, hi + lo ----
        {
            const uint4* sh = reinterpret_cast<const uint4*>(
                wh + (size_t)(oc0 + fa_oc) * KTOT + k0 + fa_half * 16);
            const uint4* sl = reinterpret_cast<const uint4*>(
                wl + (size_t)(oc0 + fa_oc) * KTOT + k0 + fa_half * 16);
            uint4 h0 = sh[0], h1 = sh[1];
            uint4 l0 = sl[0], l1 = sl[1];
            uint4* dh = reinterpret_cast<uint4*>(sAh + fa_oc * AP + fa_half * 16);
            uint4* dl = reinterpret_cast<uint4*>(sAl + fa_oc * AP + fa_half * 16);
            dh[0] = h0; dh[1] = h1;
            dl[0] = l0; dl[1] = l1;
        }

        // ---- B fill: 128 positions x 32 ic, hi + lo (coalesced over p) ----
        {
            int y = ybase + (fb_p >> 5) + dy;
            int x = (fb_p & 31) + dx;
            bool ok = ((unsigned)y < 32u) && ((unsigned)x < 32u);
            const float* src = inN + (size_t)(icb + fb_half * 16) * HWP +
                               (y << 5) + x;
            uint32_t hp[8], lp[8];
#pragma unroll
            for (int q = 0; q < 8; q++) {
                float v0 = ok ? src[(2 * q) * HWP] : 0.f;
                float v1 = ok ? src[(2 * q + 1) * HWP] : 0.f;
                __nv_bfloat16 h0 = __float2bfloat16(v0);
                __nv_bfloat16 h1 = __float2bfloat16(v1);
                __nv_bfloat16 l0 = __float2bfloat16(v0 - __bfloat162float(h0));
                __nv_bfloat16 l1 = __float2bfloat16(v1 - __bfloat162float(h1));
                hp[q] = pack_bf(h0, h1);
                lp[q] = pack_bf(l0, l1);
            }
            uint4* dh = reinterpret_cast<uint4*>(sBh + fb_p * AP + fb_half * 16);
            uint4* dl = reinterpret_cast<uint4*>(sBl + fb_p * AP + fb_half * 16);
            dh[0] = make_uint4(hp[0], hp[1], hp[2], hp[3]);
            dh[1] = make_uint4(hp[4], hp[5], hp[6], hp[7]);
            dl[0] = make_uint4(lp[0], lp[1], lp[2], lp[3]);
            dl[1] = make_uint4(lp[4], lp[5], lp[6], lp[7]);
        }
        __syncthreads();

#pragma unroll
        for (int s = 0; s < 2; ++s) {
            const int kk0 = s * 16;
            uint32_t Af[4][4], Bhf[2][4], Blf[2][4];
            // A hi fragments (4 m-tiles of 16)
#pragma unroll
            for (int mi = 0; mi < 4; mi++) {
                int row = wm * 64 + mi * 16 + a_row_off;
                ldm_x4(Af[mi], aAh + (uint32_t)(row * AP + kk0 + a_col_off) * 2);
            }
            // B hi / lo fragments (2 n-groups of 16)
#pragma unroll
            for (int g = 0; g < 2; g++) {
                int row = wn * 32 + g * 16 + b_row_off;
                uint32_t off = (uint32_t)(row * AP + kk0 + b_col_off) * 2;
                ldm_x4(Bhf[g], aBh + off);
                ldm_x4(Blf[g], aBl + off);
            }
            // pass 1: Ah * Bh
#pragma unroll
            for (int mi = 0; mi < 4; mi++)
#pragma unroll
                for (int ni = 0; ni < 4; ni++)
                    mma_bf16(C[mi][ni], Af[mi],
                             Bhf[ni >> 1][(ni & 1) * 2],
                             Bhf[ni >> 1][(ni & 1) * 2 + 1]);
            // pass 2: Ah * Bl
#pragma unroll
            for (int mi = 0; mi < 4; mi++)
#pragma unroll
                for (int ni = 0; ni < 4; ni++)
                    mma_bf16(C[mi][ni], Af[mi],
                             Blf[ni >> 1][(ni & 1) * 2],
                             Blf[ni >> 1][(ni & 1) * 2 + 1]);
            // pass 3: Al * Bh (overwrite A regs)
#pragma unroll
            for (int mi = 0; mi < 4; mi++) {
                int row = wm * 64 + mi * 16 + a_row_off;
                ldm_x4(Af[mi], aAl + (uint32_t)(row * AP + kk0 + a_col_off) * 2);
            }
#pragma unroll
            for (int mi = 0; mi < 4; mi++)
#pragma unroll
                for (int ni = 0; ni < 4; ni++)
                    mma_bf16(C[mi][ni], Af[mi],
                             Bhf[ni >> 1][(ni & 1) * 2],
                             Bhf[ni >> 1][(ni & 1) * 2 + 1]);
        }
        __syncthreads();
    }

    // ---- epilogue: direct fragment stores (+BN/ReLU for conv1) ----
    const int g = lane >> 2, t4 = lane & 3;
#pragma unroll
    for (int mi = 0; mi < 4; mi++) {
        int ocA = oc0 + wm * 64 + mi * 16 + g;
        int ocB = ocA + 8;
        float sA = 1.f, bA = 0.f, sB = 1.f, bB = 0.f;
        if (which == 1) {
            sA = g_bns[ocA]; bA = g_bnb[ocA];
            sB = g_bns[ocB]; bB = g_bnb[ocB];
        }
#pragma unroll
        for (int ni = 0; ni < 4; ni++) {
            int nn = p0 + wn * 32 + ni * 8 + t4 * 2;
            float v0 = C[mi][ni][0], v1 = C[mi][ni][1];
            float v2 = C[mi][ni][2], v3 = C[mi][ni][3];
            if (which == 1) {
                v0 = fmaxf(fmaf(v0, sA, bA), 0.f);
                v1 = fmaxf(fmaf(v1, sA, bA), 0.f);
                v2 = fmaxf(fmaf(v2, sB, bB), 0.f);
                v3 = fmaxf(fmaf(v3, sB, bB), 0.f);
            }
            *reinterpret_cast<float2*>(&outN[(size_t)ocA * HWP + nn]) =
                make_float2(v0, v1);
            *reinterpret_cast<float2*>(&outN[(size_t)ocB * HWP + nn]) =
                make_float2(v2, v3);
        }
    }
}

// ======================= assign + softmax =======================
__global__ void __launch_bounds__(128)
assign_softmax_kernel(const float* __restrict__ xenc, const float* __restrict__ wa) {
    __shared__ float s_w[8][64];
    const int n = blockIdx.x >> 3;
    const int l0 = (blockIdx.x & 7) * 128;
    const int tid = threadIdx.x;
    const int l = l0 + tid;
    const float* xN = xenc + (size_t)n * CHN * HWP;

    float s[64];
#pragma unroll
    for (int k = 0; k < 64; k++) s[k] = 0.f;
    float ss = 0.f;

    for (int c0 = 0; c0 < 512; c0 += 8) {
#pragma unroll
        for (int r = 0; r < 4; r++) {
            int idx = tid + r * 128;
            int cc = idx >> 6, k = idx & 63;
            s_w[cc][k] = wa[k * 512 + c0 + cc];
        }
        __syncthreads();
#pragma unroll
        for (int cc = 0; cc < 8; cc++) {
            float xv = xN[(c0 + cc) * HWP + l];
            ss = fmaf(xv, xv, ss);
#pragma unroll
            for (int k = 0; k < 64; k++) s[k] = fmaf(xv, s_w[cc][k], s[k]);
        }
        __syncthreads();
    }

    float invn = 1.f / fmaxf(sqrtf(ss), 1e-12f);
    g_invn[n * HWP + l] = invn;

    float mx = -1e30f;
#pragma unroll
    for (int k = 0; k < 64; k++) { s[k] *= invn; mx = fmaxf(mx, s[k]); }
    float sum = 0.f;
#pragma unroll
    for (int k = 0; k < 64; k++) { s[k] = expf(s[k] - mx); sum += s[k]; }
    float rs = 1.f / sum;
#pragma unroll
    for (int k = 0; k < 64; k++)
        g_sa[((size_t)n * 64 + k) * HWP + l] = s[k] * rs;
}

// ======================= ssum =======================
__global__ void ssum_kernel() {
    int row = blockIdx.x;
    int tid = threadIdx.x;
    const float4* p = reinterpret_cast<const float4*>(g_sa + (size_t)row * HWP);
    float4 v = p[tid];
    float t = v.x + v.y + v.z + v.w;
    __shared__ float red[256];
    red[tid] = t;
    __syncthreads();
    for (int s = 128; s > 0; s >>= 1) {
        if (tid < s) red[tid] += red[tid + s];
        __syncthreads();
    }
    if (tid == 0) g_ssum[row] = red[0];
}

// ======================= VLAD =======================
__global__ void __launch_bounds__(256)
vlad_kernel(const float* __restrict__ xenc, const float* __restrict__ cent) {
    __shared__ float s_sa[8][1024];
    __shared__ float s_in[1024];
    const int n = blockIdx.x >> 3;
    const int k0 = (blockIdx.x & 7) * 8;
    const int tid = threadIdx.x;

    for (int i = tid; i < 1024; i += 256) s_in[i] = g_invn[n * HWP + i];
    for (int i = tid; i < 8192; i += 256) {
        int kk = i >> 10, l = i & 1023;
        s_sa[kk][l] = g_sa[((size_t)n * 64 + k0 + kk) * HWP + l];
    }
    __syncthreads();

    const int warp = tid >> 5, lane = tid & 31;
    const float* xN = xenc + (size_t)n * CHN * HWP;

    for (int c = warp; c < 512; c += 8) {
        float acc[8];
#pragma unroll
        for (int kk = 0; kk < 8; kk++) acc[kk] = 0.f;
        for (int l = lane; l < 1024; l += 32) {
            float xv = xN[c * HWP + l] * s_in[l];
#pragma unroll
            for (int kk = 0; kk < 8; kk++) acc[kk] = fmaf(xv, s_sa[kk][l], acc[kk]);
        }
#pragma unroll
        for (int kk = 0; kk < 8; kk++) {
            float v = acc[kk];
#pragma unroll
            for (int o = 16; o > 0; o >>= 1) v += __shfl_down_sync(0xffffffffu, v, o);
            if (lane == 0) {
                int k = k0 + kk;
                g_vlad[((size_t)n * 64 + k) * 512 + c] =
                    v - g_ssum[n * 64 + k] * cent[k * 512 + c];
            }
        }
    }
}

// ======================= intra norm =======================
__global__ void intra_kernel(float* __restrict__ out_vlad) {
    int row = blockIdx.x;
    int tid = threadIdx.x;
    const float2* p = reinterpret_cast<const float2*>(g_vlad + (size_t)row * 512);
    float2 v = p[tid];
    float ssq = v.x * v.x + v.y * v.y;
    __shared__ float red[256];
    red[tid] = ssq;
    __syncthreads();
    for (int s = 128; s > 0; s >>= 1) {
        if (tid < s) red[tid] += red[tid + s];
        __syncthreads();
    }
    float ss = red[0];
    float inv = 1.f / fmaxf(sqrtf(ss), 1e-12f);
    float2* o = reinterpret_cast<float2*>(out_vlad + (size_t)row * 512);
    float2 w;
    w.x = v.x * inv;
    w.y = v.y * inv;
    o[tid] = w;
    if (tid == 0) g_rowss[row] = ss * inv * inv;
}

// ======================= global scale =======================
__global__ void gscale_kernel(float* __restrict__ out_vlad) {
    int n = blockIdx.x;
    int tid = threadIdx.x;
    __shared__ float red[64];
    __shared__ float gsc;
    if (tid < 64) red[tid] = g_rowss[n * 64 + tid];
    __syncthreads();
    if (tid == 0) {
        float t = 0.f;
        for (int i = 0; i < 64; i++) t += red[i];
        gsc = 1.f / fmaxf(sqrtf(t), 1e-12f);
    }
    __syncthreads();
    float g = gsc;
    float* o = out_vlad + (size_t)n * (KCL * CHN);
    for (int i = tid; i < KCL * CHN; i += 256) o[i] *= g;
}

// ======================= launcher =======================
extern "C" void kernel_launch(void* const* d_in, const int* in_sizes, int n_in,
                              void* d_out, int out_size) {
    const float* x     = (const float*)d_in[0];
    const float* w1    = (const float*)d_in[1];
    const float* gamma = (const float*)d_in[2];
    const float* beta  = (const float*)d_in[3];
    const float* mean  = (const float*)d_in[4];
    const float* var   = (const float*)d_in[5];
    const float* w2    = (const float*)d_in[6];
    const float* wa    = (const float*)d_in[7];
    const float* cent  = (const float*)d_in[8];

    float* out = (float*)d_out;
    float* out_vlad = out;
    float* out_xenc = out + (size_t)N_IMG * KCL * CHN;

    prep_kernel<<<18432, 256>>>(w1, w2, gamma, beta, mean, var);

    dim3 cgrid(8, 4, N_IMG);
    conv_mma_kernel<<<cgrid, 256>>>(x, nullptr, 1);
    conv_mma_kernel<<<cgrid, 256>>>(nullptr, out_xenc, 2);

    assign_softmax_kernel<<<N_IMG * 8, 128>>>(out_xenc, wa);
    ssum_kernel<<<N_IMG * KCL, 256>>>();
    vlad_kernel<<<N_IMG * 8, 256>>>(out_xenc, cent);
    intra_kernel<<<N_IMG * KCL, 256>>>(out_vlad);
    gscale_kernel<<<N_IMG, 256>>>(out_vlad);
}